// round 16
// baseline (speedup 1.0000x reference)
#include <cuda_runtime.h>
#include <cuda_fp16.h>

#define NN 100000
#define EE 1600000
#define HH 64
#define GG 512
#define FULL 0xffffffffu
#define TILE_N 128
#define NB 98              // ceil(NN / 1024)
#define SAS 20             // tf32 sA stride (words)
#define SBS 72             // tf32 sB stride (words)
#define SAF 140            // fused h-tile stride (floats), mult of 4, odd/32 groups

// ---------------- device scratch ----------------
__device__ int    d_deg_in[NN];
__device__ int    d_deg_out[NN];
__device__ int    d_rowptr[NN + 1];
__device__ int    d_colptr[NN + 1];
__device__ int    d_rowcur[NN];
__device__ int    d_colcur[NN];
__device__ int    d_rowedges[EE];   // edge ids grouped by source
__device__ int    d_colsrc[EE];     // source node ids grouped by target
__device__ float  d_dinv[NN];
__device__ float  d_A[NN * 32];     // aggregated edge_attr per source node
__device__ float  d_h[NN * HH];     // layer-3 agg output (pooling input)
__device__ __half d_g[NN * HH];     // g buffer A (fp16, pre-scaled by dinv)
__device__ __half d_g2[NN * HH];    // g buffer B (double buffer for fusion)
__device__ int    d_part[2 * NB];
__device__ int    d_partx[2 * NB];
// folded layer-1 weights: W @ Wg1
__device__ float d_Wn1[128 * 64];
__device__ float d_We1[32 * 64];
__device__ float d_bn1[64];
__device__ float d_be1[64];

#define FMA4(ACC, AV, B) \
    ACC.x = fmaf(AV, B.x, ACC.x); ACC.y = fmaf(AV, B.y, ACC.y); \
    ACC.z = fmaf(AV, B.z, ACC.z); ACC.w = fmaf(AV, B.w, ACC.w)

__device__ __forceinline__ unsigned f2tf(float f) {
    unsigned u;
    asm("cvt.rna.tf32.f32 %0, %1;" : "=r"(u) : "f"(f));
    return u;
}

__device__ __forceinline__ void split4(float4 f, uint4& h, uint4& l) {
    h.x = f2tf(f.x); l.x = f2tf(f.x - __uint_as_float(h.x));
    h.y = f2tf(f.y); l.y = f2tf(f.y - __uint_as_float(h.y));
    h.z = f2tf(f.z); l.z = f2tf(f.z - __uint_as_float(h.z));
    h.w = f2tf(f.w); l.w = f2tf(f.w - __uint_as_float(h.w));
}

__device__ __forceinline__ void mma_tf32(float4& d,
        unsigned a0, unsigned a1, unsigned a2, unsigned a3,
        unsigned b0, unsigned b1) {
    asm volatile(
        "mma.sync.aligned.m16n8k8.row.col.f32.tf32.tf32.f32 "
        "{%0,%1,%2,%3}, {%4,%5,%6,%7}, {%8,%9}, {%0,%1,%2,%3};\n"
        : "+f"(d.x), "+f"(d.y), "+f"(d.z), "+f"(d.w)
        : "r"(a0), "r"(a1), "r"(a2), "r"(a3), "r"(b0), "r"(b1));
}

// ---------------- fold: [Wn;We;bn;be] @ Wg1 (162 rows x 64) ----------------
__global__ void k_fold(const float* __restrict__ Wn, const float* __restrict__ We,
                       const float* __restrict__ bn, const float* __restrict__ be,
                       const float* __restrict__ Wg1) {
    __shared__ float sW[64 * 64];
    int t = threadIdx.x;  // 64 threads
    for (int i = t; i < 64 * 64; i += 64) sW[i] = Wg1[i];
    __syncthreads();
    int row = blockIdx.x;  // 0..161
    const float* src;
    float* dst;
    if (row < 128)      { src = &Wn[row * 64];          dst = &d_Wn1[row * 64]; }
    else if (row < 160) { src = &We[(row - 128) * 64];  dst = &d_We1[(row - 128) * 64]; }
    else if (row == 160){ src = bn;                     dst = d_bn1; }
    else                { src = be;                     dst = d_be1; }
    float acc = 0.0f;
#pragma unroll 16
    for (int k = 0; k < 64; k++) acc = fmaf(src[k], sW[k * 64 + t], acc);
    dst[t] = acc;
}

// ---------------- degree histograms ----------------
__global__ void k_zero() {
    int i = blockIdx.x * blockDim.x + threadIdx.x;
    int s = gridDim.x * blockDim.x;
    for (; i < NN; i += s) { d_deg_in[i] = 0; d_deg_out[i] = 0; }
}

__global__ void k_count(const int* __restrict__ ei) {
    const int4* srcs = (const int4*)ei;
    const int4* dsts = (const int4*)(ei + EE);
    int i = blockIdx.x * blockDim.x + threadIdx.x;
    int s = gridDim.x * blockDim.x;
    for (; i < EE / 4; i += s) {
        int4 r = __ldg(&srcs[i]);
        int4 c = __ldg(&dsts[i]);
        atomicAdd(&d_deg_out[r.x], 1);
        atomicAdd(&d_deg_out[r.y], 1);
        atomicAdd(&d_deg_out[r.z], 1);
        atomicAdd(&d_deg_out[r.w], 1);
        atomicAdd(&d_deg_in[c.x], 1);
        atomicAdd(&d_deg_in[c.y], 1);
        atomicAdd(&d_deg_in[c.z], 1);
        atomicAdd(&d_deg_in[c.w], 1);
    }
}

// ===== 3-phase device-wide exclusive scan of both degree arrays ==============
__global__ void k_scanpart() {
    __shared__ int red[256];
    int b = blockIdx.x;
    const int* deg = (b < NB) ? d_deg_out : d_deg_in;
    int cb = (b < NB) ? b : b - NB;
    int base = cb * 1024 + threadIdx.x * 4;
    int s = 0;
#pragma unroll
    for (int i = 0; i < 4; i++) {
        int idx = base + i;
        if (idx < NN) s += deg[idx];
    }
    red[threadIdx.x] = s;
    __syncthreads();
    for (int off = 128; off; off >>= 1) {
        if (threadIdx.x < off) red[threadIdx.x] += red[threadIdx.x + off];
        __syncthreads();
    }
    if (threadIdx.x == 0) d_part[b] = red[0];
}

__global__ void k_scanmid() {
    __shared__ int sc[128];
    int a = blockIdx.x;            // 0 = row, 1 = col
    int t = threadIdx.x;
    int v = (t < NB) ? d_part[a * NB + t] : 0;
    sc[t] = v;
    __syncthreads();
    for (int off = 1; off < 128; off <<= 1) {
        int u = (t >= off) ? sc[t - off] : 0;
        __syncthreads();
        sc[t] += u;
        __syncthreads();
    }
    if (t < NB) d_partx[a * NB + t] = sc[t] - v;   // exclusive
    if (t == NB - 1) {
        if (a == 0) d_rowptr[NN] = sc[t];
        else        d_colptr[NN] = sc[t];
    }
}

__global__ void k_writeptr() {
    __shared__ int sc[1024];
    int b = blockIdx.x;
    int is_col = (b >= NB);
    const int* deg = is_col ? d_deg_in : d_deg_out;
    int* ptr = is_col ? d_colptr : d_rowptr;
    int* cur = is_col ? d_colcur : d_rowcur;
    int cb = is_col ? b - NB : b;
    int t = threadIdx.x;
    int i = cb * 1024 + t;
    int v = (i < NN) ? deg[i] : 0;
    sc[t] = v;
    __syncthreads();
    for (int off = 1; off < 1024; off <<= 1) {
        int u = (t >= off) ? sc[t - off] : 0;
        __syncthreads();
        sc[t] += u;
        __syncthreads();
    }
    if (i < NN) {
        int excl = sc[t] - v + d_partx[b];
        ptr[i] = excl;
        cur[i] = excl;
        if (is_col) d_dinv[i] = rsqrtf((float)(v + 1));
    }
}

__global__ void k_scatter(const int* __restrict__ ei) {
    const int4* srcs = (const int4*)ei;
    const int4* dsts = (const int4*)(ei + EE);
    int i = blockIdx.x * blockDim.x + threadIdx.x;
    int s = gridDim.x * blockDim.x;
    for (; i < EE / 4; i += s) {
        int4 r = __ldg(&srcs[i]);
        int4 c = __ldg(&dsts[i]);
        int e = i * 4;
        int p0 = atomicAdd(&d_rowcur[r.x], 1);
        int p1 = atomicAdd(&d_rowcur[r.y], 1);
        int p2 = atomicAdd(&d_rowcur[r.z], 1);
        int p3 = atomicAdd(&d_rowcur[r.w], 1);
        int q0 = atomicAdd(&d_colcur[c.x], 1);
        int q1 = atomicAdd(&d_colcur[c.y], 1);
        int q2 = atomicAdd(&d_colcur[c.z], 1);
        int q3 = atomicAdd(&d_colcur[c.w], 1);
        d_rowedges[p0] = e;
        d_rowedges[p1] = e + 1;
        d_rowedges[p2] = e + 2;
        d_rowedges[p3] = e + 3;
        d_colsrc[q0] = r.x;
        d_colsrc[q1] = r.y;
        d_colsrc[q2] = r.z;
        d_colsrc[q3] = r.w;
    }
}

// ------ A[n] = sum_{e: src=n} edge_attr[e]; 4 edges/warp-iter, float4 lanes ---
__global__ void k_aggattr(const float* __restrict__ ea) {
    int n = blockIdx.x * 8 + (threadIdx.x >> 5);
    int lane = threadIdx.x & 31;
    int grp = lane >> 3;
    int gl  = lane & 7;
    if (n >= NN) return;
    int beg = d_rowptr[n], end = d_rowptr[n + 1];
    float4 acc = make_float4(0.f, 0.f, 0.f, 0.f);
    for (int base = beg; base < end; base += 32) {
        int ev = (base + lane < end) ? d_rowedges[base + lane] : -1;
#pragma unroll
        for (int t = 0; t < 8; t++) {
            int e = __shfl_sync(FULL, ev, t * 4 + grp);
            if (e >= 0) {
                float4 v = *(const float4*)&ea[e * 32 + gl * 4];
                acc.x += v.x; acc.y += v.y; acc.z += v.z; acc.w += v.w;
            }
        }
    }
#pragma unroll
    for (int off = 8; off <= 16; off <<= 1) {
        acc.x += __shfl_xor_sync(FULL, acc.x, off);
        acc.y += __shfl_xor_sync(FULL, acc.y, off);
        acc.z += __shfl_xor_sync(FULL, acc.z, off);
        acc.w += __shfl_xor_sync(FULL, acc.w, off);
    }
    if (lane < 8) *(float4*)&d_A[n * 32 + gl * 4] = acc;
}

// === 3xTF32 tensor-core GEMM (layer-1 folded), writes g1 to d_g (fp16) =======
__global__ void k_gemm1(const float* __restrict__ x) {
    __shared__ __align__(16) unsigned sAh[128 * SAS], sAl[128 * SAS];
    __shared__ __align__(16) unsigned sBh[16 * SBS], sBl[16 * SBS];
    __shared__ float sbn[64], sbe[64];
    int t = threadIdx.x;
    int nb = blockIdx.x * TILE_N;
    int w = t >> 5, lane = t & 31;
    int g = lane >> 2, tig = lane & 3;
    int ln = t >> 1;
    int kh = (t & 1) * 8;
    int gn = nb + ln;
    bool valid = (gn < NN);
    if (t < 64) { sbn[t] = d_bn1[t]; sbe[t] = d_be1[t]; }

    float4 acc[8];
#pragma unroll
    for (int i = 0; i < 8; i++) acc[i] = make_float4(0.f, 0.f, 0.f, 0.f);

    float4 wv, v[2];
    wv = ((const float4*)d_Wn1)[t];
    v[0] = valid ? *(const float4*)&x[gn * 128 + kh]     : make_float4(0.f, 0.f, 0.f, 0.f);
    v[1] = valid ? *(const float4*)&x[gn * 128 + kh + 4] : make_float4(0.f, 0.f, 0.f, 0.f);

    for (int c = 0; c < 10; c++) {
        {
            int bk = t >> 4, bc = (t & 15) * 4;
            uint4 h, l; split4(wv, h, l);
            *(uint4*)&sBh[bk * SBS + bc] = h;
            *(uint4*)&sBl[bk * SBS + bc] = l;
        }
#pragma unroll
        for (int i = 0; i < 2; i++) {
            uint4 h, l; split4(v[i], h, l);
            *(uint4*)&sAh[ln * SAS + kh + 4 * i] = h;
            *(uint4*)&sAl[ln * SAS + kh + 4 * i] = l;
        }
        __syncthreads();
        if (c < 9) {
            int cn = c + 1;
            const float4* Wv = (cn < 8) ? (const float4*)(d_Wn1 + cn * 1024)
                                        : (const float4*)(d_We1 + (cn - 8) * 1024);
            wv = Wv[t];
            if (valid) {
                if (cn < 8) {
                    v[0] = *(const float4*)&x[gn * 128 + cn * 16 + kh];
                    v[1] = *(const float4*)&x[gn * 128 + cn * 16 + kh + 4];
                } else {
                    v[0] = *(const float4*)&d_A[gn * 32 + (cn - 8) * 16 + kh];
                    v[1] = *(const float4*)&d_A[gn * 32 + (cn - 8) * 16 + kh + 4];
                }
            }
        }
        int arow = 16 * w + g;
#pragma unroll
        for (int ks = 0; ks < 2; ks++) {
            unsigned ah0 = sAh[arow * SAS + ks * 8 + tig];
            unsigned ah1 = sAh[(arow + 8) * SAS + ks * 8 + tig];
            unsigned ah2 = sAh[arow * SAS + ks * 8 + tig + 4];
            unsigned ah3 = sAh[(arow + 8) * SAS + ks * 8 + tig + 4];
            unsigned al0 = sAl[arow * SAS + ks * 8 + tig];
            unsigned al1 = sAl[(arow + 8) * SAS + ks * 8 + tig];
            unsigned al2 = sAl[arow * SAS + ks * 8 + tig + 4];
            unsigned al3 = sAl[(arow + 8) * SAS + ks * 8 + tig + 4];
#pragma unroll
            for (int j = 0; j < 8; j++) {
                unsigned bh0 = sBh[(ks * 8 + tig) * SBS + 8 * j + g];
                unsigned bh1 = sBh[(ks * 8 + tig + 4) * SBS + 8 * j + g];
                unsigned bl0 = sBl[(ks * 8 + tig) * SBS + 8 * j + g];
                unsigned bl1 = sBl[(ks * 8 + tig + 4) * SBS + 8 * j + g];
                mma_tf32(acc[j], ah0, ah1, ah2, ah3, bl0, bl1);
                mma_tf32(acc[j], al0, al1, al2, al3, bh0, bh1);
                mma_tf32(acc[j], ah0, ah1, ah2, ah3, bh0, bh1);
            }
        }
        __syncthreads();
    }
    int r0 = nb + 16 * w + g;
    int r1 = r0 + 8;
    float sc0 = 0.f, dg0 = 0.f, sc1 = 0.f, dg1 = 0.f;
    if (r0 < NN) { sc0 = d_dinv[r0]; dg0 = (float)d_deg_out[r0]; }
    if (r1 < NN) { sc1 = d_dinv[r1]; dg1 = (float)d_deg_out[r1]; }
#pragma unroll
    for (int j = 0; j < 8; j++) {
        int col = 8 * j + 2 * tig;
        float bnx = sbn[col], bny = sbn[col + 1];
        float bex = sbe[col], bey = sbe[col + 1];
        if (r0 < NN) {
            __half2 hv = __floats2half2_rn(sc0 * (acc[j].x + bnx + dg0 * bex),
                                           sc0 * (acc[j].y + bny + dg0 * bey));
            *(__half2*)&d_g[r0 * 64 + col] = hv;
        }
        if (r1 < NN) {
            __half2 hv = __floats2half2_rn(sc1 * (acc[j].z + bnx + dg1 * bex),
                                           sc1 * (acc[j].w + bny + dg1 * bey));
            *(__half2*)&d_g[r1 * 64 + col] = hv;
        }
    }
}

// === FUSED agg + gemm: h = relu(dinv*(sum gsrc) + b); gdst = dinv*(h @ W) ====
// Block owns 128 nodes. Agg phase fills transposed smem h-tile; fp32 GEMM phase
// reads it and emits fp16 g. swap selects src/dst g buffers.
__global__ void k_fusedagg(const float* __restrict__ bias,
                           const float* __restrict__ W, int swap) {
    __shared__ float sA[64 * SAF];   // h-tile transposed: sA[k*SAF + localnode]
    __shared__ float sB[32 * 64];
    const __half* gsrc = swap ? d_g2 : d_g;
    __half*       gdst = swap ? d_g  : d_g2;
    int t = threadIdx.x;
    int nb = blockIdx.x * TILE_N;
    int warp = t >> 5, lane = t & 31;
    int half = lane >> 4, hl = lane & 15;
    unsigned hmask = half ? 0xFFFF0000u : 0x0000FFFFu;

    // ---- agg phase: 8 passes, 2 nodes/warp ----
    for (int p = 0; p < 8; p++) {
        int lnid = p * 16 + warp * 2 + half;
        int n = nb + lnid;
        float4 o = make_float4(0.f, 0.f, 0.f, 0.f);
        if (n < NN) {
            uint2 sr = *(const uint2*)&gsrc[n * 64 + hl * 4];
            float2 sf0 = __half22float2(*(__half2*)&sr.x);
            float2 sf1 = __half22float2(*(__half2*)&sr.y);
            float4 acc = make_float4(sf0.x, sf0.y, sf1.x, sf1.y);  // self loop
            int beg = d_colptr[n], end = d_colptr[n + 1];
            for (int base = beg; base < end; base += 16) {
                int cnt = min(16, end - base);
                int sv = (base + hl < end) ? d_colsrc[base + hl] : 0;
                for (int tt = 0; tt < cnt; tt++) {
                    int s = __shfl_sync(hmask, sv, (half << 4) + tt);
                    uint2 raw = __ldg((const uint2*)&gsrc[s * 64 + hl * 4]);
                    float2 f0 = __half22float2(*(__half2*)&raw.x);
                    float2 f1 = __half22float2(*(__half2*)&raw.y);
                    acc.x += f0.x; acc.y += f0.y; acc.z += f1.x; acc.w += f1.y;
                }
            }
            float sc = d_dinv[n];
            float4 b = *(const float4*)&bias[hl * 4];
            o.x = fmaxf(fmaf(sc, acc.x, b.x), 0.0f);
            o.y = fmaxf(fmaf(sc, acc.y, b.y), 0.0f);
            o.z = fmaxf(fmaf(sc, acc.z, b.z), 0.0f);
            o.w = fmaxf(fmaf(sc, acc.w, b.w), 0.0f);
        }
        // store transposed (k-major) for the GEMM phase
        sA[(hl * 4 + 0) * SAF + lnid] = o.x;
        sA[(hl * 4 + 1) * SAF + lnid] = o.y;
        sA[(hl * 4 + 2) * SAF + lnid] = o.z;
        sA[(hl * 4 + 3) * SAF + lnid] = o.w;
    }
    __syncthreads();

    // ---- fp32 tiled GEMM phase: 128x64 tile, K=64 in 2 chunks ----
    int tx = t >> 4, ty = t & 15;
    float4 acc[8];
#pragma unroll
    for (int i = 0; i < 8; i++) acc[i] = make_float4(0.f, 0.f, 0.f, 0.f);
    for (int c = 0; c < 2; c++) {
        if (c > 0) __syncthreads();
        ((float4*)sB)[t]       = ((const float4*)(W + c * 2048))[t];
        ((float4*)sB)[t + 256] = ((const float4*)(W + c * 2048))[t + 256];
        __syncthreads();
#pragma unroll 8
        for (int k = 0; k < 32; k++) {
            float4 a0 = *(const float4*)&sA[(c * 32 + k) * SAF + tx * 8];
            float4 a1 = *(const float4*)&sA[(c * 32 + k) * SAF + tx * 8 + 4];
            float4 b  = *(const float4*)&sB[k * 64 + ty * 4];
            FMA4(acc[0], a0.x, b); FMA4(acc[1], a0.y, b);
            FMA4(acc[2], a0.z, b); FMA4(acc[3], a0.w, b);
            FMA4(acc[4], a1.x, b); FMA4(acc[5], a1.y, b);
            FMA4(acc[6], a1.z, b); FMA4(acc[7], a1.w, b);
        }
    }
    int nrow = nb + tx * 8;
#pragma unroll
    for (int i = 0; i < 8; i++) {
        int n = nrow + i;
        if (n < NN) {
            float sc = d_dinv[n];
            __half2 h0 = __floats2half2_rn(sc * acc[i].x, sc * acc[i].y);
            __half2 h1 = __floats2half2_rn(sc * acc[i].z, sc * acc[i].w);
            uint2 u;
            u.x = *(unsigned*)&h0;
            u.y = *(unsigned*)&h1;
            *(uint2*)&gdst[n * 64 + ty * 4] = u;
        }
    }
}

// --- layer-3 agg: h[c] = dinv[c]*(sum g[s] + g[c]) + b  (no relu) ------------
__global__ void k_agg(const float* __restrict__ bias) {
    int warp = threadIdx.x >> 5;
    int lane = threadIdx.x & 31;
    int half = lane >> 4;
    int hl   = lane & 15;
    int n = blockIdx.x * 16 + warp * 2 + half;
    if (n >= NN) return;
    unsigned hmask = half ? 0xFFFF0000u : 0x0000FFFFu;
    int beg = d_colptr[n], end = d_colptr[n + 1];
    uint2 sr = *(const uint2*)&d_g[n * 64 + hl * 4];
    float2 sf0 = __half22float2(*(__half2*)&sr.x);
    float2 sf1 = __half22float2(*(__half2*)&sr.y);
    float4 acc = make_float4(sf0.x, sf0.y, sf1.x, sf1.y);
    for (int base = beg; base < end; base += 16) {
        int cnt = min(16, end - base);
        int sv = (base + hl < end) ? d_colsrc[base + hl] : 0;
        for (int t = 0; t < cnt; t++) {
            int s = __shfl_sync(hmask, sv, (half << 4) + t);
            uint2 raw = __ldg((const uint2*)&d_g[s * 64 + hl * 4]);
            float2 f0 = __half22float2(*(__half2*)&raw.x);
            float2 f1 = __half22float2(*(__half2*)&raw.y);
            acc.x += f0.x; acc.y += f0.y; acc.z += f1.x; acc.w += f1.y;
        }
    }
    float sc = d_dinv[n];
    float4 b = *(const float4*)&bias[hl * 4];
    float4 o;
    o.x = fmaf(sc, acc.x, b.x);
    o.y = fmaf(sc, acc.y, b.y);
    o.z = fmaf(sc, acc.z, b.z);
    o.w = fmaf(sc, acc.w, b.w);
    *(float4*)&d_h[n * 64 + hl * 4] = o;
}

// ---------------- mean pool (sorted batch) + classifier ----------------
__device__ __forceinline__ int lbound(const int* a, int n, int v) {
    int lo = 0, hi = n;
    while (lo < hi) {
        int mid = (lo + hi) >> 1;
        if (a[mid] < v) lo = mid + 1; else hi = mid;
    }
    return lo;
}

__global__ void k_classifier(const int* __restrict__ batch,
                             const float* __restrict__ Wc1, const float* __restrict__ bc1,
                             const float* __restrict__ Wc2, const float* __restrict__ bc2,
                             float* __restrict__ out) {
    int g = blockIdx.x * 8 + (threadIdx.x >> 5);
    int lane = threadIdx.x & 31;
    if (g >= GG) return;
    int lo = 0, hi = 0;
    if (lane == 0) {
        lo = lbound(batch, NN, g);
        hi = lbound(batch, NN, g + 1);
    }
    lo = __shfl_sync(FULL, lo, 0);
    hi = __shfl_sync(FULL, hi, 0);
    float2 s = make_float2(0.0f, 0.0f);
    for (int n = lo; n < hi; n++) {
        float2 v = *(const float2*)&d_h[n * 64 + 2 * lane];
        s.x += v.x; s.y += v.y;
    }
    float cnt = (float)(hi - lo);
    float inv = (cnt > 0.0f) ? 1.0f / cnt : 0.0f;
    float m0 = s.x * inv, m1 = s.y * inv;
    float hid = bc1[lane];
#pragma unroll
    for (int k = 0; k < 64; k++) {
        float src = (k & 1) ? m1 : m0;
        float mk = __shfl_sync(FULL, src, k >> 1);
        hid = fmaf(mk, Wc1[k * 32 + lane], hid);
    }
    hid = fmaxf(hid, 0.0f);
    float v = hid * Wc2[lane];
#pragma unroll
    for (int off = 16; off; off >>= 1) v += __shfl_xor_sync(FULL, v, off);
    if (lane == 0) out[g] = v + bc2[0];
}

// ---------------- launch ----------------
extern "C" void kernel_launch(void* const* d_in, const int* in_sizes, int n_in,
                              void* d_out, int out_size) {
    const float* x    = (const float*)d_in[0];
    const int*   ei   = (const int*)  d_in[1];
    const float* ea   = (const float*)d_in[2];
    const int*   batch= (const int*)  d_in[3];
    const float* Wn   = (const float*)d_in[4];
    const float* bn   = (const float*)d_in[5];
    const float* We   = (const float*)d_in[6];
    const float* be   = (const float*)d_in[7];
    const float* Wg1  = (const float*)d_in[8];
    const float* bg1  = (const float*)d_in[9];
    const float* Wg2  = (const float*)d_in[10];
    const float* bg2  = (const float*)d_in[11];
    const float* Wg3  = (const float*)d_in[12];
    const float* bg3  = (const float*)d_in[13];
    const float* Wc1  = (const float*)d_in[14];
    const float* bc1  = (const float*)d_in[15];
    const float* Wc2  = (const float*)d_in[16];
    const float* bc2  = (const float*)d_in[17];
    float* out = (float*)d_out;

    const int WB  = (NN + 7) / 8;                  // warp-per-node blocks
    const int AB  = (NN + 15) / 16;                // 2-nodes-per-warp blocks
    const int GB  = (NN + TILE_N - 1) / TILE_N;    // gemm tiles

    k_fold<<<162, 64>>>(Wn, We, bn, be, Wg1);
    k_zero<<<256, 256>>>();
    k_count<<<512, 256>>>(ei);
    k_scanpart<<<2 * NB, 256>>>();
    k_scanmid<<<2, 128>>>();
    k_writeptr<<<2 * NB, 1024>>>();
    k_scatter<<<512, 256>>>(ei);
    k_aggattr<<<WB, 256>>>(ea);
    k_gemm1<<<GB, 256>>>(x);                       // g1 -> d_g (fp16)

    k_fusedagg<<<GB, 256>>>(bg1, Wg2, 0);          // d_g -> h1 -> g2 -> d_g2
    k_fusedagg<<<GB, 256>>>(bg2, Wg3, 1);          // d_g2 -> h2 -> g3 -> d_g
    k_agg<<<AB, 256>>>(bg3);                       // d_g -> h3 -> d_h

    k_classifier<<<64, 256>>>(batch, Wc1, bc1, Wc2, bc2, out);
}

// round 17
// speedup vs baseline: 1.0834x; 1.0834x over previous
#include <cuda_runtime.h>
#include <cuda_fp16.h>

#define NN 100000
#define EE 1600000
#define HH 64
#define GG 512
#define FULL 0xffffffffu
#define TILE_N 128
#define ASTRIDE 136
#define NB 98              // ceil(NN / 1024)

// ---------------- device scratch ----------------
__device__ int    d_deg_in[NN];
__device__ int    d_deg_out[NN];
__device__ int    d_rowptr[NN + 1];
__device__ int    d_colptr[NN + 1];
__device__ int    d_rowcur[NN];
__device__ int    d_colcur[NN];
__device__ int    d_rowedges[EE];   // edge ids grouped by source
__device__ int    d_colsrc[EE];     // source node ids grouped by target
__device__ float  d_dinv[NN];
__device__ float  d_A[NN * 32];     // aggregated edge_attr per source node
__device__ float  d_acc[NN * HH];   // x@Wn1 partial (fp32, stream-overlapped)
__device__ float  d_h[NN * HH];     // node features fp32 (agg output / gemm input)
__device__ __half d_g[NN * HH];     // gemm output fp16, pre-scaled by dinv[n]
__device__ int    d_part[2 * NB];
__device__ int    d_partx[2 * NB];
// folded layer-1 weights: W @ Wg1
__device__ float d_Wn1[128 * 64];
__device__ float d_We1[32 * 64];
__device__ float d_bn1[64];
__device__ float d_be1[64];

#define FMA4(ACC, AV, B) \
    ACC.x = fmaf(AV, B.x, ACC.x); ACC.y = fmaf(AV, B.y, ACC.y); \
    ACC.z = fmaf(AV, B.z, ACC.z); ACC.w = fmaf(AV, B.w, ACC.w)

__device__ __forceinline__ void store_g_half4(int n, int col4, float4 o) {
    __half2 p0 = __floats2half2_rn(o.x, o.y);
    __half2 p1 = __floats2half2_rn(o.z, o.w);
    uint2 u;
    u.x = *(unsigned*)&p0;
    u.y = *(unsigned*)&p1;
    *(uint2*)&d_g[n * 64 + col4] = u;
}

// ---------------- fold: [Wn;We;bn;be] @ Wg1 (162 rows x 64) ----------------
__global__ void k_fold(const float* __restrict__ Wn, const float* __restrict__ We,
                       const float* __restrict__ bn, const float* __restrict__ be,
                       const float* __restrict__ Wg1) {
    __shared__ float sW[64 * 64];
    int t = threadIdx.x;  // 64 threads
    for (int i = t; i < 64 * 64; i += 64) sW[i] = Wg1[i];
    __syncthreads();
    int row = blockIdx.x;  // 0..161
    const float* src;
    float* dst;
    if (row < 128)      { src = &Wn[row * 64];          dst = &d_Wn1[row * 64]; }
    else if (row < 160) { src = &We[(row - 128) * 64];  dst = &d_We1[(row - 128) * 64]; }
    else if (row == 160){ src = bn;                     dst = d_bn1; }
    else                { src = be;                     dst = d_be1; }
    float acc = 0.0f;
#pragma unroll 16
    for (int k = 0; k < 64; k++) acc = fmaf(src[k], sW[k * 64 + t], acc);
    dst[t] = acc;
}

// ---------------- degree histograms ----------------
__global__ void k_zero() {
    int i = blockIdx.x * blockDim.x + threadIdx.x;
    int s = gridDim.x * blockDim.x;
    for (; i < NN; i += s) { d_deg_in[i] = 0; d_deg_out[i] = 0; }
}

__global__ void k_count(const int* __restrict__ ei) {
    const int4* srcs = (const int4*)ei;
    const int4* dsts = (const int4*)(ei + EE);
    int i = blockIdx.x * blockDim.x + threadIdx.x;
    int s = gridDim.x * blockDim.x;
    for (; i < EE / 4; i += s) {
        int4 r = __ldg(&srcs[i]);
        int4 c = __ldg(&dsts[i]);
        atomicAdd(&d_deg_out[r.x], 1);
        atomicAdd(&d_deg_out[r.y], 1);
        atomicAdd(&d_deg_out[r.z], 1);
        atomicAdd(&d_deg_out[r.w], 1);
        atomicAdd(&d_deg_in[c.x], 1);
        atomicAdd(&d_deg_in[c.y], 1);
        atomicAdd(&d_deg_in[c.z], 1);
        atomicAdd(&d_deg_in[c.w], 1);
    }
}

// ===== 3-phase device-wide exclusive scan of both degree arrays ==============
__global__ void k_scanpart() {
    __shared__ int red[256];
    int b = blockIdx.x;
    const int* deg = (b < NB) ? d_deg_out : d_deg_in;
    int cb = (b < NB) ? b : b - NB;
    int base = cb * 1024 + threadIdx.x * 4;
    int s = 0;
#pragma unroll
    for (int i = 0; i < 4; i++) {
        int idx = base + i;
        if (idx < NN) s += deg[idx];
    }
    red[threadIdx.x] = s;
    __syncthreads();
    for (int off = 128; off; off >>= 1) {
        if (threadIdx.x < off) red[threadIdx.x] += red[threadIdx.x + off];
        __syncthreads();
    }
    if (threadIdx.x == 0) d_part[b] = red[0];
}

__global__ void k_scanmid() {
    __shared__ int sc[128];
    int a = blockIdx.x;            // 0 = row, 1 = col
    int t = threadIdx.x;
    int v = (t < NB) ? d_part[a * NB + t] : 0;
    sc[t] = v;
    __syncthreads();
    for (int off = 1; off < 128; off <<= 1) {
        int u = (t >= off) ? sc[t - off] : 0;
        __syncthreads();
        sc[t] += u;
        __syncthreads();
    }
    if (t < NB) d_partx[a * NB + t] = sc[t] - v;   // exclusive
    if (t == NB - 1) {
        if (a == 0) d_rowptr[NN] = sc[t];
        else        d_colptr[NN] = sc[t];
    }
}

__global__ void k_writeptr() {
    __shared__ int sc[1024];
    int b = blockIdx.x;
    int is_col = (b >= NB);
    const int* deg = is_col ? d_deg_in : d_deg_out;
    int* ptr = is_col ? d_colptr : d_rowptr;
    int* cur = is_col ? d_colcur : d_rowcur;
    int cb = is_col ? b - NB : b;
    int t = threadIdx.x;
    int i = cb * 1024 + t;
    int v = (i < NN) ? deg[i] : 0;
    sc[t] = v;
    __syncthreads();
    for (int off = 1; off < 1024; off <<= 1) {
        int u = (t >= off) ? sc[t - off] : 0;
        __syncthreads();
        sc[t] += u;
        __syncthreads();
    }
    if (i < NN) {
        int excl = sc[t] - v + d_partx[b];
        ptr[i] = excl;
        cur[i] = excl;
        if (is_col) d_dinv[i] = rsqrtf((float)(v + 1));
    }
}

__global__ void k_scatter(const int* __restrict__ ei) {
    const int4* srcs = (const int4*)ei;
    const int4* dsts = (const int4*)(ei + EE);
    int i = blockIdx.x * blockDim.x + threadIdx.x;
    int s = gridDim.x * blockDim.x;
    for (; i < EE / 4; i += s) {
        int4 r = __ldg(&srcs[i]);
        int4 c = __ldg(&dsts[i]);
        int e = i * 4;
        int p0 = atomicAdd(&d_rowcur[r.x], 1);
        int p1 = atomicAdd(&d_rowcur[r.y], 1);
        int p2 = atomicAdd(&d_rowcur[r.z], 1);
        int p3 = atomicAdd(&d_rowcur[r.w], 1);
        int q0 = atomicAdd(&d_colcur[c.x], 1);
        int q1 = atomicAdd(&d_colcur[c.y], 1);
        int q2 = atomicAdd(&d_colcur[c.z], 1);
        int q3 = atomicAdd(&d_colcur[c.w], 1);
        d_rowedges[p0] = e;
        d_rowedges[p1] = e + 1;
        d_rowedges[p2] = e + 2;
        d_rowedges[p3] = e + 3;
        d_colsrc[q0] = r.x;
        d_colsrc[q1] = r.y;
        d_colsrc[q2] = r.z;
        d_colsrc[q3] = r.w;
    }
}

// ------ A[n] = sum_{e: src=n} edge_attr[e]; 4 edges/warp-iter, float4 lanes ---
__global__ void k_aggattr(const float* __restrict__ ea) {
    int n = blockIdx.x * 8 + (threadIdx.x >> 5);
    int lane = threadIdx.x & 31;
    int grp = lane >> 3;
    int gl  = lane & 7;
    if (n >= NN) return;
    int beg = d_rowptr[n], end = d_rowptr[n + 1];
    float4 acc = make_float4(0.f, 0.f, 0.f, 0.f);
    for (int base = beg; base < end; base += 32) {
        int ev = (base + lane < end) ? d_rowedges[base + lane] : -1;
#pragma unroll
        for (int t = 0; t < 8; t++) {
            int e = __shfl_sync(FULL, ev, t * 4 + grp);
            if (e >= 0) {
                float4 v = *(const float4*)&ea[e * 32 + gl * 4];
                acc.x += v.x; acc.y += v.y; acc.z += v.z; acc.w += v.w;
            }
        }
    }
#pragma unroll
    for (int off = 8; off <= 16; off <<= 1) {
        acc.x += __shfl_xor_sync(FULL, acc.x, off);
        acc.y += __shfl_xor_sync(FULL, acc.y, off);
        acc.z += __shfl_xor_sync(FULL, acc.z, off);
        acc.w += __shfl_xor_sync(FULL, acc.w, off);
    }
    if (lane < 8) *(float4*)&d_A[n * 32 + gl * 4] = acc;
}

// === tiled SGEMM (stream-overlapped): d_acc = x @ Wn1  (K=128) ===============
__global__ void k_xgemm(const float* __restrict__ x) {
    __shared__ float sA[32 * ASTRIDE];
    __shared__ float sB[32 * 64];
    int t = threadIdx.x;
    int nb = blockIdx.x * TILE_N;
    int tx = t >> 4, ty = t & 15;
    int ln = t >> 1;
    int kh = (t & 1) * 16;
    int gn = nb + ln;

    float4 acc[8];
#pragma unroll
    for (int i = 0; i < 8; i++) acc[i] = make_float4(0.f, 0.f, 0.f, 0.f);

    for (int c = 0; c < 4; c++) {
        __syncthreads();
        const float4* Wv = (const float4*)(d_Wn1 + c * 2048);
        ((float4*)sB)[t]       = Wv[t];
        ((float4*)sB)[t + 256] = Wv[t + 256];

        float4 v[4];
#pragma unroll
        for (int i = 0; i < 4; i++) {
            v[i] = (gn < NN) ? *(const float4*)&x[gn * 128 + c * 32 + kh + 4 * i]
                             : make_float4(0.f, 0.f, 0.f, 0.f);
        }
#pragma unroll
        for (int i = 0; i < 4; i++) {
            sA[(kh + 4 * i + 0) * ASTRIDE + ln] = v[i].x;
            sA[(kh + 4 * i + 1) * ASTRIDE + ln] = v[i].y;
            sA[(kh + 4 * i + 2) * ASTRIDE + ln] = v[i].z;
            sA[(kh + 4 * i + 3) * ASTRIDE + ln] = v[i].w;
        }
        __syncthreads();
#pragma unroll 8
        for (int k = 0; k < 32; k++) {
            float4 a0 = *(const float4*)&sA[k * ASTRIDE + tx * 8];
            float4 a1 = *(const float4*)&sA[k * ASTRIDE + tx * 8 + 4];
            float4 b  = *(const float4*)&sB[k * 64 + ty * 4];
            FMA4(acc[0], a0.x, b); FMA4(acc[1], a0.y, b);
            FMA4(acc[2], a0.z, b); FMA4(acc[3], a0.w, b);
            FMA4(acc[4], a1.x, b); FMA4(acc[5], a1.y, b);
            FMA4(acc[6], a1.z, b); FMA4(acc[7], a1.w, b);
        }
    }
    int nrow = nb + tx * 8;
#pragma unroll
    for (int i = 0; i < 8; i++) {
        int n = nrow + i;
        if (n < NN) *(float4*)&d_acc[n * 64 + ty * 4] = acc[i];
    }
}

// === finish layer-1: g = dinv * (d_acc + A@We1 + bn1 + deg*be1)  (K=32) ======
__global__ void k_gemm1A() {
    __shared__ float sA[32 * ASTRIDE];
    __shared__ float sB[32 * 64];
    int t = threadIdx.x;
    int nb = blockIdx.x * TILE_N;
    int tx = t >> 4, ty = t & 15;
    int ln = t >> 1;
    int kh = (t & 1) * 16;
    int gn = nb + ln;

    {
        const float4* Wv = (const float4*)d_We1;
        ((float4*)sB)[t]       = Wv[t];
        ((float4*)sB)[t + 256] = Wv[t + 256];
        float4 v[4];
#pragma unroll
        for (int i = 0; i < 4; i++) {
            v[i] = (gn < NN) ? *(const float4*)&d_A[gn * 32 + kh + 4 * i]
                             : make_float4(0.f, 0.f, 0.f, 0.f);
        }
#pragma unroll
        for (int i = 0; i < 4; i++) {
            sA[(kh + 4 * i + 0) * ASTRIDE + ln] = v[i].x;
            sA[(kh + 4 * i + 1) * ASTRIDE + ln] = v[i].y;
            sA[(kh + 4 * i + 2) * ASTRIDE + ln] = v[i].z;
            sA[(kh + 4 * i + 3) * ASTRIDE + ln] = v[i].w;
        }
    }
    __syncthreads();

    float4 acc[8];
#pragma unroll
    for (int i = 0; i < 8; i++) acc[i] = make_float4(0.f, 0.f, 0.f, 0.f);
#pragma unroll 8
    for (int k = 0; k < 32; k++) {
        float4 a0 = *(const float4*)&sA[k * ASTRIDE + tx * 8];
        float4 a1 = *(const float4*)&sA[k * ASTRIDE + tx * 8 + 4];
        float4 b  = *(const float4*)&sB[k * 64 + ty * 4];
        FMA4(acc[0], a0.x, b); FMA4(acc[1], a0.y, b);
        FMA4(acc[2], a0.z, b); FMA4(acc[3], a0.w, b);
        FMA4(acc[4], a1.x, b); FMA4(acc[5], a1.y, b);
        FMA4(acc[6], a1.z, b); FMA4(acc[7], a1.w, b);
    }
    float4 bnv = *(const float4*)&d_bn1[ty * 4];
    float4 bev = *(const float4*)&d_be1[ty * 4];
    int nrow = nb + tx * 8;
#pragma unroll
    for (int i = 0; i < 8; i++) {
        int n = nrow + i;
        if (n < NN) {
            float dg = (float)d_deg_out[n];
            float sc = d_dinv[n];
            float4 xa = *(const float4*)&d_acc[n * 64 + ty * 4];
            float4 o;
            o.x = sc * (acc[i].x + xa.x + bnv.x + dg * bev.x);
            o.y = sc * (acc[i].y + xa.y + bnv.y + dg * bev.y);
            o.z = sc * (acc[i].z + xa.z + bnv.z + dg * bev.z);
            o.w = sc * (acc[i].w + xa.w + bnv.w + dg * bev.w);
            store_g_half4(n, ty * 4, o);
        }
    }
}

// ====== tiled SGEMM: g[n] = dinv[n] * (h[n] @ W)  (64x64), fp16 out ==========
__global__ void k_gemm64(const float* __restrict__ W) {
    __shared__ float sA[32 * ASTRIDE];
    __shared__ float sB[32 * 64];
    int t = threadIdx.x;
    int nb = blockIdx.x * TILE_N;
    int tx = t >> 4, ty = t & 15;
    int ln = t >> 1;
    int kh = (t & 1) * 16;
    int gn = nb + ln;

    float4 acc[8];
#pragma unroll
    for (int i = 0; i < 8; i++) acc[i] = make_float4(0.f, 0.f, 0.f, 0.f);

    for (int c = 0; c < 2; c++) {
        __syncthreads();
        const float4* Wv = (const float4*)(W + c * 2048);
        ((float4*)sB)[t]       = Wv[t];
        ((float4*)sB)[t + 256] = Wv[t + 256];

        float4 v[4];
#pragma unroll
        for (int i = 0; i < 4; i++)
            v[i] = (gn < NN) ? *(const float4*)&d_h[gn * 64 + c * 32 + kh + 4 * i]
                             : make_float4(0.f, 0.f, 0.f, 0.f);
#pragma unroll
        for (int i = 0; i < 4; i++) {
            sA[(kh + 4 * i + 0) * ASTRIDE + ln] = v[i].x;
            sA[(kh + 4 * i + 1) * ASTRIDE + ln] = v[i].y;
            sA[(kh + 4 * i + 2) * ASTRIDE + ln] = v[i].z;
            sA[(kh + 4 * i + 3) * ASTRIDE + ln] = v[i].w;
        }
        __syncthreads();
#pragma unroll 8
        for (int k = 0; k < 32; k++) {
            float4 a0 = *(const float4*)&sA[k * ASTRIDE + tx * 8];
            float4 a1 = *(const float4*)&sA[k * ASTRIDE + tx * 8 + 4];
            float4 b  = *(const float4*)&sB[k * 64 + ty * 4];
            FMA4(acc[0], a0.x, b); FMA4(acc[1], a0.y, b);
            FMA4(acc[2], a0.z, b); FMA4(acc[3], a0.w, b);
            FMA4(acc[4], a1.x, b); FMA4(acc[5], a1.y, b);
            FMA4(acc[6], a1.z, b); FMA4(acc[7], a1.w, b);
        }
    }
    int nrow = nb + tx * 8;
#pragma unroll
    for (int i = 0; i < 8; i++) {
        int n = nrow + i;
        if (n < NN) {
            float sc = d_dinv[n];
            float4 o;
            o.x = sc * acc[i].x; o.y = sc * acc[i].y;
            o.z = sc * acc[i].z; o.w = sc * acc[i].w;
            store_g_half4(n, ty * 4, o);
        }
    }
}

// --- h[c] = act( dinv[c]*(sum g[s] + g[c]) + b ); 2 nodes/warp, fp16 gathers --
__global__ void k_agg(const float* __restrict__ bias, int do_relu) {
    int warp = threadIdx.x >> 5;
    int lane = threadIdx.x & 31;
    int half = lane >> 4;
    int hl   = lane & 15;
    int n = blockIdx.x * 16 + warp * 2 + half;
    if (n >= NN) return;
    unsigned hmask = half ? 0xFFFF0000u : 0x0000FFFFu;
    int beg = d_colptr[n], end = d_colptr[n + 1];
    uint2 sr = *(const uint2*)&d_g[n * 64 + hl * 4];
    float2 sf0 = __half22float2(*(__half2*)&sr.x);
    float2 sf1 = __half22float2(*(__half2*)&sr.y);
    float4 acc = make_float4(sf0.x, sf0.y, sf1.x, sf1.y);
    for (int base = beg; base < end; base += 16) {
        int cnt = min(16, end - base);
        int sv = (base + hl < end) ? d_colsrc[base + hl] : 0;
        for (int t = 0; t < cnt; t++) {
            int s = __shfl_sync(hmask, sv, (half << 4) + t);
            uint2 raw = __ldg((const uint2*)&d_g[s * 64 + hl * 4]);
            float2 f0 = __half22float2(*(__half2*)&raw.x);
            float2 f1 = __half22float2(*(__half2*)&raw.y);
            acc.x += f0.x; acc.y += f0.y; acc.z += f1.x; acc.w += f1.y;
        }
    }
    float sc = d_dinv[n];
    float4 b = *(const float4*)&bias[hl * 4];
    float4 o;
    o.x = fmaf(sc, acc.x, b.x);
    o.y = fmaf(sc, acc.y, b.y);
    o.z = fmaf(sc, acc.z, b.z);
    o.w = fmaf(sc, acc.w, b.w);
    if (do_relu) {
        o.x = fmaxf(o.x, 0.0f); o.y = fmaxf(o.y, 0.0f);
        o.z = fmaxf(o.z, 0.0f); o.w = fmaxf(o.w, 0.0f);
    }
    *(float4*)&d_h[n * 64 + hl * 4] = o;
}

// ---------------- mean pool (sorted batch) + classifier ----------------
__device__ __forceinline__ int lbound(const int* a, int n, int v) {
    int lo = 0, hi = n;
    while (lo < hi) {
        int mid = (lo + hi) >> 1;
        if (a[mid] < v) lo = mid + 1; else hi = mid;
    }
    return lo;
}

__global__ void k_classifier(const int* __restrict__ batch,
                             const float* __restrict__ Wc1, const float* __restrict__ bc1,
                             const float* __restrict__ Wc2, const float* __restrict__ bc2,
                             float* __restrict__ out) {
    int g = blockIdx.x * 8 + (threadIdx.x >> 5);
    int lane = threadIdx.x & 31;
    if (g >= GG) return;
    int lo = 0, hi = 0;
    if (lane == 0) {
        lo = lbound(batch, NN, g);
        hi = lbound(batch, NN, g + 1);
    }
    lo = __shfl_sync(FULL, lo, 0);
    hi = __shfl_sync(FULL, hi, 0);
    float2 s = make_float2(0.0f, 0.0f);
    for (int n = lo; n < hi; n++) {
        float2 v = *(const float2*)&d_h[n * 64 + 2 * lane];
        s.x += v.x; s.y += v.y;
    }
    float cnt = (float)(hi - lo);
    float inv = (cnt > 0.0f) ? 1.0f / cnt : 0.0f;
    float m0 = s.x * inv, m1 = s.y * inv;
    float hid = bc1[lane];
#pragma unroll
    for (int k = 0; k < 64; k++) {
        float src = (k & 1) ? m1 : m0;
        float mk = __shfl_sync(FULL, src, k >> 1);
        hid = fmaf(mk, Wc1[k * 32 + lane], hid);
    }
    hid = fmaxf(hid, 0.0f);
    float v = hid * Wc2[lane];
#pragma unroll
    for (int off = 16; off; off >>= 1) v += __shfl_xor_sync(FULL, v, off);
    if (lane == 0) out[g] = v + bc2[0];
}

// ---------------- launch ----------------
extern "C" void kernel_launch(void* const* d_in, const int* in_sizes, int n_in,
                              void* d_out, int out_size) {
    const float* x    = (const float*)d_in[0];
    const int*   ei   = (const int*)  d_in[1];
    const float* ea   = (const float*)d_in[2];
    const int*   batch= (const int*)  d_in[3];
    const float* Wn   = (const float*)d_in[4];
    const float* bn   = (const float*)d_in[5];
    const float* We   = (const float*)d_in[6];
    const float* be   = (const float*)d_in[7];
    const float* Wg1  = (const float*)d_in[8];
    const float* bg1  = (const float*)d_in[9];
    const float* Wg2  = (const float*)d_in[10];
    const float* bg2  = (const float*)d_in[11];
    const float* Wg3  = (const float*)d_in[12];
    const float* bg3  = (const float*)d_in[13];
    const float* Wc1  = (const float*)d_in[14];
    const float* bc1  = (const float*)d_in[15];
    const float* Wc2  = (const float*)d_in[16];
    const float* bc2  = (const float*)d_in[17];
    float* out = (float*)d_out;

    const int WB  = (NN + 7) / 8;
    const int AB  = (NN + 15) / 16;
    const int GB  = (NN + TILE_N - 1) / TILE_N;

    // one-time stream/event setup (first call is the non-captured correctness
    // run; during capture only record/wait appear, which are capturable)
    static cudaStream_t s2 = nullptr;
    static cudaEvent_t evFork = nullptr, evJoin = nullptr;
    if (s2 == nullptr) {
        cudaStreamCreateWithFlags(&s2, cudaStreamNonBlocking);
        cudaEventCreateWithFlags(&evFork, cudaEventDisableTiming);
        cudaEventCreateWithFlags(&evJoin, cudaEventDisableTiming);
    }

    k_fold<<<162, 64>>>(Wn, We, bn, be, Wg1);

    // fork: x@Wn1 on s2, overlapped with the graph build below
    cudaEventRecord(evFork, 0);
    cudaStreamWaitEvent(s2, evFork, 0);
    k_xgemm<<<GB, 256, 0, s2>>>(x);
    cudaEventRecord(evJoin, s2);

    k_zero<<<256, 256>>>();
    k_count<<<512, 256>>>(ei);
    k_scanpart<<<2 * NB, 256>>>();
    k_scanmid<<<2, 128>>>();
    k_writeptr<<<2 * NB, 1024>>>();
    k_scatter<<<512, 256>>>(ei);
    k_aggattr<<<WB, 256>>>(ea);

    // join, then finish layer-1 g
    cudaStreamWaitEvent(0, evJoin, 0);
    k_gemm1A<<<GB, 256>>>();

    k_agg<<<AB, 256>>>(bg1, 1);
    k_gemm64<<<GB, 256>>>(Wg2);
    k_agg<<<AB, 256>>>(bg2, 1);
    k_gemm64<<<GB, 256>>>(Wg3);
    k_agg<<<AB, 256>>>(bg3, 0);

    k_classifier<<<64, 256>>>(batch, Wc1, bc1, Wc2, bc2, out);
}